// round 4
// baseline (speedup 1.0000x reference)
#include <cuda_runtime.h>
#include <math.h>

#define D_DIM 1024
#define B_DIM 128
#define C_DIM 1000
#define EPSF  1e-6f

// Scratch (device globals — no allocation allowed)
__device__ float g_Xl[B_DIM * D_DIM];   // x @ L
__device__ float g_Ml[C_DIM * D_DIM];   // mu @ L
__device__ float g_nX[B_DIM];           // ||Xl_b||^2
__device__ float g_bx[B_DIM];           // beta . x_b
__device__ float g_nM[C_DIM];           // ||Ml_c||^2
__device__ float g_bm[C_DIM];           // beta . mu_c

// ---------------------------------------------------------------------------
// proj: C[M,1024] = A[M,1024] @ L[1024,1024]  (L lower-triangular: k-loop
// starts at the output-column tile, since L[d,k]==0 for d<k)
// BM=64, BN=64, BK=16, 256 threads, 4x4 per thread.
// ---------------------------------------------------------------------------
__global__ void proj_gemm_kernel(const float* __restrict__ A,
                                 const float* __restrict__ Lm,
                                 int M, int sel)
{
    float* __restrict__ C = sel ? g_Ml : g_Xl;
    const int BM = 64, BN = 64, BK = 16;
    __shared__ float As[BK][BM + 1];
    __shared__ float Bs[BK][BN + 4];

    const int bm  = blockIdx.y * BM;
    const int bn  = blockIdx.x * BN;
    const int tid = threadIdx.x;
    const int tx  = tid & 15;          // 0..15 col group
    const int ty  = tid >> 4;          // 0..15 row group

    // A loader: thread -> (row am, 4 contiguous k at ak)
    const int am  = tid >> 2;          // 0..63
    const int ak  = (tid & 3) * 4;     // 0,4,8,12
    // L loader: thread -> (k row bk, 4 contiguous cols at bn4)
    const int bk  = tid >> 4;          // 0..15
    const int bn4 = (tid & 15) * 4;    // 0..60

    float acc[4][4] = {};

    for (int kt = bn; kt < D_DIM; kt += BK) {   // triangular skip: kt >= bn
        float4 av = make_float4(0.f, 0.f, 0.f, 0.f);
        if (bm + am < M)
            av = *reinterpret_cast<const float4*>(&A[(bm + am) * D_DIM + kt + ak]);
        As[ak + 0][am] = av.x; As[ak + 1][am] = av.y;
        As[ak + 2][am] = av.z; As[ak + 3][am] = av.w;

        float4 bv = *reinterpret_cast<const float4*>(&Lm[(kt + bk) * D_DIM + bn + bn4]);
        Bs[bk][bn4 + 0] = bv.x; Bs[bk][bn4 + 1] = bv.y;
        Bs[bk][bn4 + 2] = bv.z; Bs[bk][bn4 + 3] = bv.w;
        __syncthreads();

        #pragma unroll
        for (int k = 0; k < BK; k++) {
            float ra[4], rb[4];
            #pragma unroll
            for (int i = 0; i < 4; i++) ra[i] = As[k][ty * 4 + i];
            #pragma unroll
            for (int j = 0; j < 4; j++) rb[j] = Bs[k][tx * 4 + j];
            #pragma unroll
            for (int i = 0; i < 4; i++)
                #pragma unroll
                for (int j = 0; j < 4; j++)
                    acc[i][j] += ra[i] * rb[j];
        }
        __syncthreads();
    }

    #pragma unroll
    for (int i = 0; i < 4; i++) {
        int r = bm + ty * 4 + i;
        if (r < M) {
            #pragma unroll
            for (int j = 0; j < 4; j++)
                C[r * D_DIM + bn + tx * 4 + j] = acc[i][j];
        }
    }
}

// ---------------------------------------------------------------------------
// rowstats: per-row  ||proj_r||^2  and  beta . orig_r
// ---------------------------------------------------------------------------
__global__ void rowstats_kernel(const float* __restrict__ orig,
                                const float* __restrict__ beta,
                                int sel)
{
    const float* proj = sel ? g_Ml : g_Xl;
    float* nrm = sel ? g_nM : g_nX;
    float* bd  = sel ? g_bm : g_bx;

    const int r   = blockIdx.x;
    const int tid = threadIdx.x;   // 256 threads

    const float4* pr  = reinterpret_cast<const float4*>(&proj[r * D_DIM]);
    const float4* orow = reinterpret_cast<const float4*>(&orig[r * D_DIM]);
    const float4* be  = reinterpret_cast<const float4*>(beta);

    float s = 0.f, b = 0.f;
    for (int k = tid; k < D_DIM / 4; k += 256) {
        float4 v = pr[k];
        s += v.x * v.x + v.y * v.y + v.z * v.z + v.w * v.w;
        float4 o = orow[k], bb = be[k];
        b += o.x * bb.x + o.y * bb.y + o.z * bb.z + o.w * bb.w;
    }
    #pragma unroll
    for (int off = 16; off; off >>= 1) {
        s += __shfl_down_sync(0xffffffffu, s, off);
        b += __shfl_down_sync(0xffffffffu, b, off);
    }
    __shared__ float ss[8], sb[8];
    if ((tid & 31) == 0) { ss[tid >> 5] = s; sb[tid >> 5] = b; }
    __syncthreads();
    if (tid == 0) {
        float S = 0.f, Bv = 0.f;
        #pragma unroll
        for (int w = 0; w < 8; w++) { S += ss[w]; Bv += sb[w]; }
        nrm[r] = S; bd[r] = Bv;
    }
}

// ---------------------------------------------------------------------------
// cross + epilogue: out[b,c] = -scale*( sqrt(nX[b]-2*Xl_b.Ml_c+nM[c]+EPS)
//                                       + lmbda*sqrt((bx[b]-bm[c])^2+EPS) )
// NT GEMM: BM=32, BN=64, BK=16, 256 threads, 2x4 per thread.
// ---------------------------------------------------------------------------
__global__ void cross_kernel(const float* __restrict__ lmbda_p,
                             const float* __restrict__ scale_p,
                             float* __restrict__ out)
{
    const int BM = 32, BN = 64, BK = 16;
    __shared__ float As[BK][BM + 2];
    __shared__ float Bs[BK][BN + 4];

    const int bm  = blockIdx.y * BM;
    const int bn  = blockIdx.x * BN;
    const int tid = threadIdx.x;
    const int tx  = tid & 15;
    const int ty  = tid >> 4;          // 0..15

    // A loader: float2 per thread (32x16 = 512 elems)
    const int am  = tid >> 3;          // 0..31
    const int ak  = (tid & 7) * 2;     // 0..14
    // B loader: float4 per thread (64x16 = 1024 elems)
    const int bn_ = tid >> 2;          // 0..63
    const int bk4 = (tid & 3) * 4;

    float acc[2][4] = {};

    for (int kt = 0; kt < D_DIM; kt += BK) {
        float2 av = *reinterpret_cast<const float2*>(&g_Xl[(bm + am) * D_DIM + kt + ak]);
        As[ak + 0][am] = av.x; As[ak + 1][am] = av.y;

        float4 bv = make_float4(0.f, 0.f, 0.f, 0.f);
        if (bn + bn_ < C_DIM)
            bv = *reinterpret_cast<const float4*>(&g_Ml[(bn + bn_) * D_DIM + kt + bk4]);
        Bs[bk4 + 0][bn_] = bv.x; Bs[bk4 + 1][bn_] = bv.y;
        Bs[bk4 + 2][bn_] = bv.z; Bs[bk4 + 3][bn_] = bv.w;
        __syncthreads();

        #pragma unroll
        for (int k = 0; k < BK; k++) {
            float ra0 = As[k][ty * 2 + 0];
            float ra1 = As[k][ty * 2 + 1];
            float rb[4];
            #pragma unroll
            for (int j = 0; j < 4; j++) rb[j] = Bs[k][tx * 4 + j];
            #pragma unroll
            for (int j = 0; j < 4; j++) {
                acc[0][j] += ra0 * rb[j];
                acc[1][j] += ra1 * rb[j];
            }
        }
        __syncthreads();
    }

    const float lm = *lmbda_p;
    const float sc = *scale_p;

    #pragma unroll
    for (int i = 0; i < 2; i++) {
        int b = bm + ty * 2 + i;
        float nx = g_nX[b];
        float bx = g_bx[b];
        #pragma unroll
        for (int j = 0; j < 4; j++) {
            int c = bn + tx * 4 + j;
            if (c < C_DIM) {
                float q   = nx - 2.f * acc[i][j] + g_nM[c];
                float bdv = bx - g_bm[c];
                out[b * C_DIM + c] =
                    -sc * (sqrtf(fmaxf(q, 0.f) + EPSF)
                           + lm * sqrtf(bdv * bdv + EPSF));
            }
        }
    }
}

// ---------------------------------------------------------------------------
extern "C" void kernel_launch(void* const* d_in, const int* in_sizes, int n_in,
                              void* d_out, int out_size)
{
    const float* x     = (const float*)d_in[0];
    const float* mu    = (const float*)d_in[1];
    const float* beta  = (const float*)d_in[2];
    const float* L     = (const float*)d_in[3];
    const float* lmbda = (const float*)d_in[4];
    const float* scale = (const float*)d_in[5];
    float* out = (float*)d_out;

    dim3 gX(D_DIM / 64, (B_DIM + 63) / 64);   // (16, 2)
    proj_gemm_kernel<<<gX, 256>>>(x, L, B_DIM, 0);

    dim3 gM(D_DIM / 64, (C_DIM + 63) / 64);   // (16, 16)
    proj_gemm_kernel<<<gM, 256>>>(mu, L, C_DIM, 1);

    rowstats_kernel<<<B_DIM, 256>>>(x, beta, 0);
    rowstats_kernel<<<C_DIM, 256>>>(mu, beta, 1);

    dim3 gC((C_DIM + 63) / 64, B_DIM / 32);   // (16, 4)
    cross_kernel<<<gC, 256>>>(lmbda, scale, out);
}

// round 5
// speedup vs baseline: 1.4739x; 1.4739x over previous
#include <cuda_runtime.h>
#include <math.h>

#define D_DIM 1024
#define B_DIM 128
#define C_DIM 1000
#define EPSF  1e-6f

// Scratch (device globals — no allocation allowed)
__device__ float g_Xl[B_DIM * D_DIM];   // x @ L
__device__ float g_Ml[C_DIM * D_DIM];   // mu @ L
__device__ float g_nX[B_DIM];           // ||Xl_b||^2
__device__ float g_bx[B_DIM];           // beta . x_b
__device__ float g_nM[C_DIM];           // ||Ml_c||^2
__device__ float g_bm[C_DIM];           // beta . mu_c

// ---------------------------------------------------------------------------
// proj: C[M,1024] = A[M,1024] @ L  (L lower-triangular: k starts at bn)
// BM=64, BN=64, BK=16, 256 threads, 4x4/thread, double-buffered smem.
// grid.y in [0,16): mu tiles -> g_Ml ; grid.y in [16,18): x tiles -> g_Xl.
// ---------------------------------------------------------------------------
__global__ void proj_kernel(const float* __restrict__ x,
                            const float* __restrict__ mu,
                            const float* __restrict__ Lm)
{
    const int BM = 64, BN = 64, BK = 16;
    // +4 pad keeps rows 272B (16B-multiple) -> LDS.128 stays aligned
    __shared__ __align__(16) float As[2][BK][BM + 4];
    __shared__ __align__(16) float Bs[2][BK][BN + 4];

    const float* A;
    float* C;
    int M, bm;
    if (blockIdx.y < 16) { A = mu; C = g_Ml; M = C_DIM; bm = blockIdx.y * BM; }
    else                 { A = x;  C = g_Xl; M = B_DIM; bm = (blockIdx.y - 16) * BM; }

    const int bn  = blockIdx.x * BN;
    const int tid = threadIdx.x;
    const int tx  = tid & 15;          // 0..15
    const int ty  = tid >> 4;          // 0..15

    // A loader: (row am, 4 contiguous k at ak)
    const int am  = tid >> 2;          // 0..63
    const int ak  = (tid & 3) * 4;     // 0,4,8,12
    // L loader: (k row bk, 4 contiguous cols at bn4)
    const int bk  = tid >> 4;          // 0..15
    const int bn4 = (tid & 15) * 4;    // 0..60

    const bool arow_ok = (bm + am) < M;
    const float* Ap = A + (bm + am) * D_DIM + ak;      // + kt
    const float* Lp = Lm + bk * D_DIM + bn + bn4;      // + kt*D_DIM

    const int niter = (D_DIM - bn) / BK;               // triangular skip

    // prologue: tile 0 (kt = bn)
    {
        float4 av = make_float4(0.f, 0.f, 0.f, 0.f);
        if (arow_ok) av = *reinterpret_cast<const float4*>(Ap + bn);
        As[0][ak + 0][am] = av.x; As[0][ak + 1][am] = av.y;
        As[0][ak + 2][am] = av.z; As[0][ak + 3][am] = av.w;
        float4 bv = *reinterpret_cast<const float4*>(Lp + (size_t)bn * D_DIM);
        Bs[0][bk][bn4 + 0] = bv.x; Bs[0][bk][bn4 + 1] = bv.y;
        Bs[0][bk][bn4 + 2] = bv.z; Bs[0][bk][bn4 + 3] = bv.w;
    }
    __syncthreads();

    float acc[4][4] = {};

    for (int it = 0; it < niter; ++it) {
        const int buf = it & 1;
        const bool more = (it + 1) < niter;
        float4 nav = make_float4(0.f, 0.f, 0.f, 0.f), nbv;
        if (more) {
            const int ktn = bn + (it + 1) * BK;
            if (arow_ok) nav = *reinterpret_cast<const float4*>(Ap + ktn);
            nbv = *reinterpret_cast<const float4*>(Lp + (size_t)ktn * D_DIM);
        }

        #pragma unroll
        for (int k = 0; k < BK; k++) {
            float4 ra = *reinterpret_cast<const float4*>(&As[buf][k][ty * 4]);
            float4 rb = *reinterpret_cast<const float4*>(&Bs[buf][k][tx * 4]);
            float a0 = ra.x, a1 = ra.y, a2 = ra.z, a3 = ra.w;
            acc[0][0] += a0 * rb.x; acc[0][1] += a0 * rb.y;
            acc[0][2] += a0 * rb.z; acc[0][3] += a0 * rb.w;
            acc[1][0] += a1 * rb.x; acc[1][1] += a1 * rb.y;
            acc[1][2] += a1 * rb.z; acc[1][3] += a1 * rb.w;
            acc[2][0] += a2 * rb.x; acc[2][1] += a2 * rb.y;
            acc[2][2] += a2 * rb.z; acc[2][3] += a2 * rb.w;
            acc[3][0] += a3 * rb.x; acc[3][1] += a3 * rb.y;
            acc[3][2] += a3 * rb.z; acc[3][3] += a3 * rb.w;
        }

        if (more) {
            const int nb = buf ^ 1;
            As[nb][ak + 0][am] = nav.x; As[nb][ak + 1][am] = nav.y;
            As[nb][ak + 2][am] = nav.z; As[nb][ak + 3][am] = nav.w;
            Bs[nb][bk][bn4 + 0] = nbv.x; Bs[nb][bk][bn4 + 1] = nbv.y;
            Bs[nb][bk][bn4 + 2] = nbv.z; Bs[nb][bk][bn4 + 3] = nbv.w;
        }
        __syncthreads();
    }

    #pragma unroll
    for (int i = 0; i < 4; i++) {
        const int r = bm + ty * 4 + i;
        if (r < M) {
            float4 o = make_float4(acc[i][0], acc[i][1], acc[i][2], acc[i][3]);
            *reinterpret_cast<float4*>(&C[(size_t)r * D_DIM + bn + tx * 4]) = o;
        }
    }
}

// ---------------------------------------------------------------------------
// fused rowstats: blocks [0,128) -> x rows, [128,1128) -> mu rows.
// 256 threads: each handles exactly one float4 (1024 = 256*4).
// ---------------------------------------------------------------------------
__global__ void rowstats_kernel(const float* __restrict__ x,
                                const float* __restrict__ mu,
                                const float* __restrict__ beta)
{
    const float* proj; const float* orig; float* nrm; float* bd; int row;
    if (blockIdx.x < B_DIM) {
        proj = g_Xl; orig = x;  nrm = g_nX; bd = g_bx; row = blockIdx.x;
    } else {
        proj = g_Ml; orig = mu; nrm = g_nM; bd = g_bm; row = blockIdx.x - B_DIM;
    }
    const int tid = threadIdx.x;   // 256

    float4 v  = reinterpret_cast<const float4*>(proj + (size_t)row * D_DIM)[tid];
    float4 o  = reinterpret_cast<const float4*>(orig + (size_t)row * D_DIM)[tid];
    float4 bb = reinterpret_cast<const float4*>(beta)[tid];

    float s = v.x * v.x + v.y * v.y + v.z * v.z + v.w * v.w;
    float b = o.x * bb.x + o.y * bb.y + o.z * bb.z + o.w * bb.w;

    #pragma unroll
    for (int off = 16; off; off >>= 1) {
        s += __shfl_down_sync(0xffffffffu, s, off);
        b += __shfl_down_sync(0xffffffffu, b, off);
    }
    __shared__ float ss[8], sb[8];
    if ((tid & 31) == 0) { ss[tid >> 5] = s; sb[tid >> 5] = b; }
    __syncthreads();
    if (tid == 0) {
        float S = 0.f, Bv = 0.f;
        #pragma unroll
        for (int w = 0; w < 8; w++) { S += ss[w]; Bv += sb[w]; }
        nrm[row] = S; bd[row] = Bv;
    }
}

// ---------------------------------------------------------------------------
// cross + epilogue: out[b,c] = -scale*( sqrt(nX[b]-2*Xl_b.Ml_c+nM[c]+EPS)
//                                       + lmbda*sqrt((bx[b]-bm[c])^2+EPS) )
// NT GEMM: BM=32, BN=64, BK=16, 256 threads, 2x4/thread, double-buffered.
// ---------------------------------------------------------------------------
__global__ void cross_kernel(const float* __restrict__ lmbda_p,
                             const float* __restrict__ scale_p,
                             float* __restrict__ out)
{
    const int BM = 32, BN = 64, BK = 16;
    __shared__ __align__(16) float As[2][BK][BM + 4];   // stride 36*4=144B (16B mult)
    __shared__ __align__(16) float Bs[2][BK][BN + 4];

    const int bm  = blockIdx.y * BM;
    const int bn  = blockIdx.x * BN;
    const int tid = threadIdx.x;
    const int tx  = tid & 15;
    const int ty  = tid >> 4;          // 0..15

    // A loader: float2 per thread (32x16 = 512 elems)
    const int am  = tid >> 3;          // 0..31
    const int ak  = (tid & 7) * 2;     // 0..14
    // B loader: float4 per thread (64x16 = 1024 elems), k-contiguous from Ml rows
    const int bn_ = tid >> 2;          // 0..63
    const int bk4 = (tid & 3) * 4;     // 0..12

    const bool brow_ok = (bn + bn_) < C_DIM;
    const float* Xp = g_Xl + (size_t)(bm + am) * D_DIM + ak;   // + kt
    const float* Mp = g_Ml + (size_t)(bn + bn_) * D_DIM + bk4; // + kt

    const int niter = D_DIM / BK;   // 64

    {
        float2 av = *reinterpret_cast<const float2*>(Xp);
        As[0][ak + 0][am] = av.x; As[0][ak + 1][am] = av.y;
        float4 bv = make_float4(0.f, 0.f, 0.f, 0.f);
        if (brow_ok) bv = *reinterpret_cast<const float4*>(Mp);
        Bs[0][bk4 + 0][bn_] = bv.x; Bs[0][bk4 + 1][bn_] = bv.y;
        Bs[0][bk4 + 2][bn_] = bv.z; Bs[0][bk4 + 3][bn_] = bv.w;
    }
    __syncthreads();

    float acc[2][4] = {};

    for (int it = 0; it < niter; ++it) {
        const int buf = it & 1;
        const bool more = (it + 1) < niter;
        float2 nav; float4 nbv = make_float4(0.f, 0.f, 0.f, 0.f);
        if (more) {
            const int ktn = (it + 1) * BK;
            nav = *reinterpret_cast<const float2*>(Xp + ktn);
            if (brow_ok) nbv = *reinterpret_cast<const float4*>(Mp + ktn);
        }

        #pragma unroll
        for (int k = 0; k < BK; k++) {
            float2 ra = *reinterpret_cast<const float2*>(&As[buf][k][ty * 2]);
            float4 rb = *reinterpret_cast<const float4*>(&Bs[buf][k][tx * 4]);
            acc[0][0] += ra.x * rb.x; acc[0][1] += ra.x * rb.y;
            acc[0][2] += ra.x * rb.z; acc[0][3] += ra.x * rb.w;
            acc[1][0] += ra.y * rb.x; acc[1][1] += ra.y * rb.y;
            acc[1][2] += ra.y * rb.z; acc[1][3] += ra.y * rb.w;
        }

        if (more) {
            const int nb = buf ^ 1;
            As[nb][ak + 0][am] = nav.x; As[nb][ak + 1][am] = nav.y;
            Bs[nb][bk4 + 0][bn_] = nbv.x; Bs[nb][bk4 + 1][bn_] = nbv.y;
            Bs[nb][bk4 + 2][bn_] = nbv.z; Bs[nb][bk4 + 3][bn_] = nbv.w;
        }
        __syncthreads();
    }

    const float lm = *lmbda_p;
    const float sc = *scale_p;

    #pragma unroll
    for (int i = 0; i < 2; i++) {
        const int b = bm + ty * 2 + i;
        const float nx = g_nX[b];
        const float bx = g_bx[b];
        #pragma unroll
        for (int j = 0; j < 4; j++) {
            const int c = bn + tx * 4 + j;
            if (c < C_DIM) {
                float q   = nx - 2.f * acc[i][j] + g_nM[c];
                float bdv = bx - g_bm[c];
                out[(size_t)b * C_DIM + c] =
                    -sc * (sqrtf(fmaxf(q, 0.f) + EPSF)
                           + lm * sqrtf(bdv * bdv + EPSF));
            }
        }
    }
}

// ---------------------------------------------------------------------------
extern "C" void kernel_launch(void* const* d_in, const int* in_sizes, int n_in,
                              void* d_out, int out_size)
{
    const float* x     = (const float*)d_in[0];
    const float* mu    = (const float*)d_in[1];
    const float* beta  = (const float*)d_in[2];
    const float* L     = (const float*)d_in[3];
    const float* lmbda = (const float*)d_in[4];
    const float* scale = (const float*)d_in[5];
    float* out = (float*)d_out;

    dim3 gP(D_DIM / 64, 18);                 // y<16: mu tiles, y>=16: x tiles
    proj_kernel<<<gP, 256>>>(x, mu, L);

    rowstats_kernel<<<B_DIM + C_DIM, 256>>>(x, mu, beta);

    dim3 gC((C_DIM + 63) / 64, B_DIM / 32);  // (16, 4)
    cross_kernel<<<gC, 256>>>(lmbda, scale, out);
}

// round 6
// speedup vs baseline: 2.0241x; 1.3733x over previous
#include <cuda_runtime.h>
#include <math.h>

#define D_DIM 1024
#define B_DIM 128
#define C_DIM 1000
#define EPSF  1e-6f

// Scratch (device globals — no allocation allowed)
__device__ float g_Xl[B_DIM * D_DIM];   // x @ L
__device__ float g_Ml[C_DIM * D_DIM];   // mu @ L
__device__ float g_nX[B_DIM];           // ||Xl_b||^2
__device__ float g_bx[B_DIM];           // beta . x_b
__device__ float g_nM[C_DIM];           // ||Ml_c||^2
__device__ float g_bm[C_DIM];           // beta . mu_c
__device__ float g_pc[4][B_DIM * C_DIM]; // split-K partial cross dots

// ---------------------------------------------------------------------------
// proj: C[M,1024] = A[M,1024] @ L  (L lower-triangular: k starts at bn)
// BM=32, BN=64, BK=16, 128 threads, 4x4/thread, double-buffered smem.
// grid.y in [0,32): mu tiles -> g_Ml ; grid.y in [32,36): x tiles -> g_Xl.
// ---------------------------------------------------------------------------
__global__ __launch_bounds__(128, 8)
void proj_kernel(const float* __restrict__ x,
                 const float* __restrict__ mu,
                 const float* __restrict__ Lm)
{
    const int BN = 64, BK = 16;
    __shared__ __align__(16) float As[2][BK][32 + 4];   // row 144B (16B mult)
    __shared__ __align__(16) float Bs[2][BK][BN + 4];   // row 272B (16B mult)

    const float* A;
    float* C;
    int M, bm;
    if (blockIdx.y < 32) { A = mu; C = g_Ml; M = C_DIM; bm = blockIdx.y * 32; }
    else                 { A = x;  C = g_Xl; M = B_DIM; bm = (blockIdx.y - 32) * 32; }

    const int bn  = blockIdx.x * BN;
    const int tid = threadIdx.x;
    const int tx  = tid & 15;          // 0..15 -> cols tx*4..tx*4+3
    const int ty  = tid >> 4;          // 0..7  -> rows ty*4..ty*4+3

    // A loader: 32 rows x 16 k = 512 floats = 128 x float4
    const int am  = tid >> 2;          // 0..31
    const int ak  = (tid & 3) * 4;     // 0,4,8,12
    // L loader: 16 k x 64 cols = 1024 floats = 128 x (2 x float4)
    const int bk  = tid >> 4;          // 0..7  (also bk+8)
    const int bn4 = (tid & 15) * 4;    // 0..60

    const bool arow_ok = (bm + am) < M;
    const float* Ap  = A  + (size_t)(bm + am) * D_DIM + ak;          // + kt
    const float* Lp0 = Lm + (size_t)bk       * D_DIM + bn + bn4;     // + kt*D
    const float* Lp1 = Lm + (size_t)(bk + 8) * D_DIM + bn + bn4;     // + kt*D

    const int niter = (D_DIM - bn) / BK;               // triangular skip

    // prologue: tile 0 (kt = bn)
    {
        float4 av = make_float4(0.f, 0.f, 0.f, 0.f);
        if (arow_ok) av = *reinterpret_cast<const float4*>(Ap + bn);
        As[0][ak + 0][am] = av.x; As[0][ak + 1][am] = av.y;
        As[0][ak + 2][am] = av.z; As[0][ak + 3][am] = av.w;
        float4 b0 = *reinterpret_cast<const float4*>(Lp0 + (size_t)bn * D_DIM);
        float4 b1 = *reinterpret_cast<const float4*>(Lp1 + (size_t)bn * D_DIM);
        Bs[0][bk][bn4 + 0] = b0.x; Bs[0][bk][bn4 + 1] = b0.y;
        Bs[0][bk][bn4 + 2] = b0.z; Bs[0][bk][bn4 + 3] = b0.w;
        Bs[0][bk + 8][bn4 + 0] = b1.x; Bs[0][bk + 8][bn4 + 1] = b1.y;
        Bs[0][bk + 8][bn4 + 2] = b1.z; Bs[0][bk + 8][bn4 + 3] = b1.w;
    }
    __syncthreads();

    float acc[4][4] = {};

    for (int it = 0; it < niter; ++it) {
        const int buf = it & 1;
        const bool more = (it + 1) < niter;
        float4 nav = make_float4(0.f, 0.f, 0.f, 0.f), nb0, nb1;
        if (more) {
            const int ktn = bn + (it + 1) * BK;
            if (arow_ok) nav = *reinterpret_cast<const float4*>(Ap + ktn);
            nb0 = *reinterpret_cast<const float4*>(Lp0 + (size_t)ktn * D_DIM);
            nb1 = *reinterpret_cast<const float4*>(Lp1 + (size_t)ktn * D_DIM);
        }

        #pragma unroll
        for (int k = 0; k < BK; k++) {
            float4 ra = *reinterpret_cast<const float4*>(&As[buf][k][ty * 4]);
            float4 rb = *reinterpret_cast<const float4*>(&Bs[buf][k][tx * 4]);
            acc[0][0] += ra.x * rb.x; acc[0][1] += ra.x * rb.y;
            acc[0][2] += ra.x * rb.z; acc[0][3] += ra.x * rb.w;
            acc[1][0] += ra.y * rb.x; acc[1][1] += ra.y * rb.y;
            acc[1][2] += ra.y * rb.z; acc[1][3] += ra.y * rb.w;
            acc[2][0] += ra.z * rb.x; acc[2][1] += ra.z * rb.y;
            acc[2][2] += ra.z * rb.z; acc[2][3] += ra.z * rb.w;
            acc[3][0] += ra.w * rb.x; acc[3][1] += ra.w * rb.y;
            acc[3][2] += ra.w * rb.z; acc[3][3] += ra.w * rb.w;
        }

        if (more) {
            const int nb = buf ^ 1;
            As[nb][ak + 0][am] = nav.x; As[nb][ak + 1][am] = nav.y;
            As[nb][ak + 2][am] = nav.z; As[nb][ak + 3][am] = nav.w;
            Bs[nb][bk][bn4 + 0] = nb0.x; Bs[nb][bk][bn4 + 1] = nb0.y;
            Bs[nb][bk][bn4 + 2] = nb0.z; Bs[nb][bk][bn4 + 3] = nb0.w;
            Bs[nb][bk + 8][bn4 + 0] = nb1.x; Bs[nb][bk + 8][bn4 + 1] = nb1.y;
            Bs[nb][bk + 8][bn4 + 2] = nb1.z; Bs[nb][bk + 8][bn4 + 3] = nb1.w;
        }
        __syncthreads();
    }

    #pragma unroll
    for (int i = 0; i < 4; i++) {
        const int r = bm + ty * 4 + i;
        if (r < M) {
            float4 o = make_float4(acc[i][0], acc[i][1], acc[i][2], acc[i][3]);
            *reinterpret_cast<float4*>(&C[(size_t)r * D_DIM + bn + tx * 4]) = o;
        }
    }
}

// ---------------------------------------------------------------------------
// fused rowstats: blocks [0,128) -> x rows, [128,1128) -> mu rows.
// 256 threads: each handles exactly one float4 (1024 = 256*4).
// ---------------------------------------------------------------------------
__global__ void rowstats_kernel(const float* __restrict__ x,
                                const float* __restrict__ mu,
                                const float* __restrict__ beta)
{
    const float* proj; const float* orig; float* nrm; float* bd; int row;
    if (blockIdx.x < B_DIM) {
        proj = g_Xl; orig = x;  nrm = g_nX; bd = g_bx; row = blockIdx.x;
    } else {
        proj = g_Ml; orig = mu; nrm = g_nM; bd = g_bm; row = blockIdx.x - B_DIM;
    }
    const int tid = threadIdx.x;   // 256

    float4 v  = reinterpret_cast<const float4*>(proj + (size_t)row * D_DIM)[tid];
    float4 o  = reinterpret_cast<const float4*>(orig + (size_t)row * D_DIM)[tid];
    float4 bb = reinterpret_cast<const float4*>(beta)[tid];

    float s = v.x * v.x + v.y * v.y + v.z * v.z + v.w * v.w;
    float b = o.x * bb.x + o.y * bb.y + o.z * bb.z + o.w * bb.w;

    #pragma unroll
    for (int off = 16; off; off >>= 1) {
        s += __shfl_down_sync(0xffffffffu, s, off);
        b += __shfl_down_sync(0xffffffffu, b, off);
    }
    __shared__ float ss[8], sb[8];
    if ((tid & 31) == 0) { ss[tid >> 5] = s; sb[tid >> 5] = b; }
    __syncthreads();
    if (tid == 0) {
        float S = 0.f, Bv = 0.f;
        #pragma unroll
        for (int w = 0; w < 8; w++) { S += ss[w]; Bv += sb[w]; }
        nrm[row] = S; bd[row] = Bv;
    }
}

// ---------------------------------------------------------------------------
// cross partial GEMM: split-K=4. Each block computes a 32x64 tile of
// dot(Xl_b, Ml_c) over k in [z*256, (z+1)*256) -> g_pc[z].
// BM=32, BN=64, BK=16, 128 threads, 4x4/thread, double-buffered.
// ---------------------------------------------------------------------------
__global__ __launch_bounds__(128, 8)
void cross_part_kernel()
{
    const int BN = 64, BK = 16;
    __shared__ __align__(16) float As[2][BK][32 + 4];
    __shared__ __align__(16) float Bs[2][BK][BN + 4];

    const int bm = blockIdx.y * 32;
    const int bn = blockIdx.x * BN;
    const int kz = blockIdx.z;                 // 0..3
    const int k0 = kz * 256;

    const int tid = threadIdx.x;
    const int tx  = tid & 15;
    const int ty  = tid >> 4;                  // 0..7

    // A loader: 32 rows x 16 k = 128 x float4
    const int am  = tid >> 2;                  // 0..31
    const int ak  = (tid & 3) * 4;
    // B loader: 64 rows (c) x 16 k = 128 x (2 x float4); rows bn_ and bn_+32
    const int bn_ = tid >> 2;                  // 0..31
    const int bk4 = (tid & 3) * 4;

    const bool bok0 = (bn + bn_)      < C_DIM;
    const bool bok1 = (bn + bn_ + 32) < C_DIM;
    const float* Xp  = g_Xl + (size_t)(bm + am) * D_DIM + k0 + ak;
    const float* Mp0 = g_Ml + (size_t)(bn + bn_)      * D_DIM + k0 + bk4;
    const float* Mp1 = g_Ml + (size_t)(bn + bn_ + 32) * D_DIM + k0 + bk4;

    const int niter = 256 / BK;                // 16

    {
        float4 av = *reinterpret_cast<const float4*>(Xp);
        As[0][ak + 0][am] = av.x; As[0][ak + 1][am] = av.y;
        As[0][ak + 2][am] = av.z; As[0][ak + 3][am] = av.w;
        float4 b0 = make_float4(0.f,0.f,0.f,0.f), b1 = make_float4(0.f,0.f,0.f,0.f);
        if (bok0) b0 = *reinterpret_cast<const float4*>(Mp0);
        if (bok1) b1 = *reinterpret_cast<const float4*>(Mp1);
        Bs[0][bk4 + 0][bn_] = b0.x; Bs[0][bk4 + 1][bn_] = b0.y;
        Bs[0][bk4 + 2][bn_] = b0.z; Bs[0][bk4 + 3][bn_] = b0.w;
        Bs[0][bk4 + 0][bn_ + 32] = b1.x; Bs[0][bk4 + 1][bn_ + 32] = b1.y;
        Bs[0][bk4 + 2][bn_ + 32] = b1.z; Bs[0][bk4 + 3][bn_ + 32] = b1.w;
    }
    __syncthreads();

    float acc[4][4] = {};

    for (int it = 0; it < niter; ++it) {
        const int buf = it & 1;
        const bool more = (it + 1) < niter;
        float4 nav, nb0 = make_float4(0.f,0.f,0.f,0.f), nb1 = make_float4(0.f,0.f,0.f,0.f);
        if (more) {
            const int ktn = (it + 1) * BK;
            nav = *reinterpret_cast<const float4*>(Xp + ktn);
            if (bok0) nb0 = *reinterpret_cast<const float4*>(Mp0 + ktn);
            if (bok1) nb1 = *reinterpret_cast<const float4*>(Mp1 + ktn);
        }

        #pragma unroll
        for (int k = 0; k < BK; k++) {
            float4 ra = *reinterpret_cast<const float4*>(&As[buf][k][ty * 4]);
            float4 rb = *reinterpret_cast<const float4*>(&Bs[buf][k][tx * 4]);
            acc[0][0] += ra.x * rb.x; acc[0][1] += ra.x * rb.y;
            acc[0][2] += ra.x * rb.z; acc[0][3] += ra.x * rb.w;
            acc[1][0] += ra.y * rb.x; acc[1][1] += ra.y * rb.y;
            acc[1][2] += ra.y * rb.z; acc[1][3] += ra.y * rb.w;
            acc[2][0] += ra.z * rb.x; acc[2][1] += ra.z * rb.y;
            acc[2][2] += ra.z * rb.z; acc[2][3] += ra.z * rb.w;
            acc[3][0] += ra.w * rb.x; acc[3][1] += ra.w * rb.y;
            acc[3][2] += ra.w * rb.z; acc[3][3] += ra.w * rb.w;
        }

        if (more) {
            const int nb = buf ^ 1;
            As[nb][ak + 0][am] = nav.x; As[nb][ak + 1][am] = nav.y;
            As[nb][ak + 2][am] = nav.z; As[nb][ak + 3][am] = nav.w;
            Bs[nb][bk4 + 0][bn_] = nb0.x; Bs[nb][bk4 + 1][bn_] = nb0.y;
            Bs[nb][bk4 + 2][bn_] = nb0.z; Bs[nb][bk4 + 3][bn_] = nb0.w;
            Bs[nb][bk4 + 0][bn_ + 32] = nb1.x; Bs[nb][bk4 + 1][bn_ + 32] = nb1.y;
            Bs[nb][bk4 + 2][bn_ + 32] = nb1.z; Bs[nb][bk4 + 3][bn_ + 32] = nb1.w;
        }
        __syncthreads();
    }

    float* __restrict__ pc = g_pc[kz];
    #pragma unroll
    for (int i = 0; i < 4; i++) {
        const int b = bm + ty * 4 + i;       // always < 128
        #pragma unroll
        for (int j = 0; j < 4; j++) {
            const int c = bn + tx * 4 + j;
            if (c < C_DIM) pc[(size_t)b * C_DIM + c] = acc[i][j];
        }
    }
}

// ---------------------------------------------------------------------------
// epilogue: reduce split-K partials + final math.
// 128000 elements = 500 blocks x 256 threads.
// ---------------------------------------------------------------------------
__global__ void epilogue_kernel(const float* __restrict__ lmbda_p,
                                const float* __restrict__ scale_p,
                                float* __restrict__ out)
{
    const int idx = blockIdx.x * 256 + threadIdx.x;   // < 128000 exactly
    const int b = idx / C_DIM;
    const int c = idx - b * C_DIM;

    const float dot = g_pc[0][idx] + g_pc[1][idx] + g_pc[2][idx] + g_pc[3][idx];
    const float q   = g_nX[b] - 2.f * dot + g_nM[c];
    const float bdv = g_bx[b] - g_bm[c];
    const float lm  = *lmbda_p;
    const float sc  = *scale_p;
    out[idx] = -sc * (sqrtf(fmaxf(q, 0.f) + EPSF)
                      + lm * sqrtf(bdv * bdv + EPSF));
}

// ---------------------------------------------------------------------------
extern "C" void kernel_launch(void* const* d_in, const int* in_sizes, int n_in,
                              void* d_out, int out_size)
{
    const float* x     = (const float*)d_in[0];
    const float* mu    = (const float*)d_in[1];
    const float* beta  = (const float*)d_in[2];
    const float* L     = (const float*)d_in[3];
    const float* lmbda = (const float*)d_in[4];
    const float* scale = (const float*)d_in[5];
    float* out = (float*)d_out;

    dim3 gP(D_DIM / 64, 36);                 // y<32: mu tiles, y>=32: x tiles
    proj_kernel<<<gP, 128>>>(x, mu, L);

    rowstats_kernel<<<B_DIM + C_DIM, 256>>>(x, mu, beta);

    dim3 gC(16, 4, 4);                       // 256 blocks, split-K=4
    cross_part_kernel<<<gC, 128>>>();

    epilogue_kernel<<<500, 256>>>(lmbda, scale, out);
}